// round 6
// baseline (speedup 1.0000x reference)
#include <cuda_runtime.h>
#include <cuda_bf16.h>
#include <stdint.h>
#include <float.h>

#define DECAY 0.99f
#define OMD   0.01f
#define EPS   1e-5f
#define NROWS 32768
#define DDIM  128
#define KCODES 1024
#define BM 128                   /* rows per CTA  */
#define BN 128                   /* codes per tile */
#define NBLK (KCODES / BN)       /* 8 */
#define DTHREADS 512
#define THREADS 256
#define MARGIN 0.008f

/* smem byte offsets */
#define OFF_X1   0               /* 128x128 bf16 swizzled, 32KB */
#define OFF_X2   32768
#define OFF_E0   65536           /* buf0: e1 (32KB) + e2 (32KB) */
#define OFF_E1   131072          /* buf1 */
#define OFF_ES2  196608          /* es2[2][128] floats */
#define SMEM_TOTAL (196608 + 1024)

typedef unsigned long long ull;

/* scratch (no device mallocs allowed) */
__device__ float         g_e2[KCODES];
__device__ int           g_idx[NROWS];
__device__ float         g_sm[KCODES];
__device__ __nv_bfloat16 g_eb1[KCODES * DDIM];
__device__ __nv_bfloat16 g_eb2[KCODES * DDIM];
__device__ unsigned char g_flag[NROWS];

/* ------------------------------------------------------------------ */
__device__ __forceinline__ uint32_t smem_u32(const void* p) {
    uint32_t a;
    asm("{ .reg .u64 t; cvta.to.shared.u64 t, %1; cvt.u32.u64 %0, t; }"
        : "=r"(a) : "l"(p));
    return a;
}
__device__ __forceinline__ uint32_t sw128(uint32_t off) {
    return off ^ ((off >> 3) & 0x70);
}
/* blocked SW128 atom layout for [128 rows x 128 bf16] K-major tile */
__device__ __forceinline__ uint32_t blk_off(int r, int c) {
    return ((uint32_t)((c >> 6) * 16 + (r >> 3)) << 10)
         + ((uint32_t)(r & 7) << 7) + ((uint32_t)(c & 63) << 1);
}
__device__ __forceinline__ uint32_t pack_bf(__nv_bfloat16 lo, __nv_bfloat16 hi) {
    uint16_t l = *reinterpret_cast<uint16_t*>(&lo);
    uint16_t h = *reinterpret_cast<uint16_t*>(&hi);
    return ((uint32_t)h << 16) | l;
}
__device__ __forceinline__ void ldsm4(uint32_t* r, uint32_t addr) {
    asm volatile("ldmatrix.sync.aligned.m8n8.x4.shared.b16 {%0,%1,%2,%3}, [%4];"
                 : "=r"(r[0]), "=r"(r[1]), "=r"(r[2]), "=r"(r[3]) : "r"(addr));
}
__device__ __forceinline__ void mma16816(float* d, const uint32_t* a,
                                         uint32_t b0, uint32_t b1) {
    asm volatile(
        "mma.sync.aligned.m16n8k16.row.col.f32.bf16.bf16.f32 "
        "{%0,%1,%2,%3}, {%4,%5,%6,%7}, {%8,%9}, {%0,%1,%2,%3};"
        : "+f"(d[0]), "+f"(d[1]), "+f"(d[2]), "+f"(d[3])
        : "r"(a[0]), "r"(a[1]), "r"(a[2]), "r"(a[3]), "r"(b0), "r"(b1));
}
#define CP16(dst, src) \
    asm volatile("cp.async.cg.shared.global [%0], [%1], 16;" \
                 :: "r"(dst), "l"(src) : "memory")
#define CP_COMMIT() asm volatile("cp.async.commit_group;" ::: "memory")
#define CP_WAIT(n)  asm volatile("cp.async.wait_group %0;" :: "n"(n) : "memory")

/* ------------------------------------------------------------------ */
/* embed prep: bf16 split + ||e||^2. one warp per code.                */
/* ------------------------------------------------------------------ */
__global__ void e_split_kernel(const float* __restrict__ embed) {
    int code = (blockIdx.x * blockDim.x + threadIdx.x) >> 5;
    int lane = threadIdx.x & 31;
    if (code >= KCODES) return;
    float4 a = *((const float4*)(embed + (size_t)code * DDIM) + lane);
    float f[4] = {a.x, a.y, a.z, a.w};
    __nv_bfloat16 b1[4], b2[4];
    float s = 0.f;
    #pragma unroll
    for (int j = 0; j < 4; j++) {
        s += f[j] * f[j];
        b1[j] = __float2bfloat16_rn(f[j]);
        float r = f[j] - __bfloat162float(b1[j]);
        b2[j] = __float2bfloat16_rn(r);
    }
    uint32_t* d1 = (uint32_t*)(g_eb1 + (size_t)code * DDIM + lane * 4);
    uint32_t* d2 = (uint32_t*)(g_eb2 + (size_t)code * DDIM + lane * 4);
    d1[0] = pack_bf(b1[0], b1[1]); d1[1] = pack_bf(b1[2], b1[3]);
    d2[0] = pack_bf(b2[0], b2[1]); d2[1] = pack_bf(b2[2], b2[3]);
    #pragma unroll
    for (int o = 16; o; o >>= 1) s += __shfl_xor_sync(0xffffffffu, s, o);
    if (lane == 0) g_e2[code] = s;
}

/* ------------------------------------------------------------------ */
/* mma.sync distance + approx argmax with top-2 margin flag            */
/* 512 threads, 16 warps, 4x4 warp grid, warp tile 32x32               */
/* ------------------------------------------------------------------ */
__global__ void __launch_bounds__(DTHREADS)
dist_mma_kernel(const float* __restrict__ x, float* __restrict__ out_ind) {
    extern __shared__ char smem[];
    const uint32_t sb = smem_u32(smem);
    const int tid  = threadIdx.x;
    const int wid  = tid >> 5, lane = tid & 31;
    const int wr   = wid & 3, wc = wid >> 2;      /* warp grid 4x4 */
    const int gid  = lane >> 2, tig = lane & 3;
    const int lrow = lane & 15, lcol = (lane >> 4) << 3;
    const int row0 = blockIdx.x * BM;
    float* es2 = (float*)(smem + OFF_ES2);        /* [2][128] */

    /* x tile: split to bf16 pair, store swizzled. 2048 chunks / 512 thr */
    #pragma unroll
    for (int it = 0; it < 4; it++) {
        int i = tid + it * DTHREADS;
        int row = i >> 4, c8 = i & 15;
        const float* xp = x + (size_t)(row0 + row) * DDIM + c8 * 8;
        float4 fa = *(const float4*)xp;
        float4 fb = *(const float4*)(xp + 4);
        float f[8] = {fa.x, fa.y, fa.z, fa.w, fb.x, fb.y, fb.z, fb.w};
        uint32_t u1[4], u2[4];
        #pragma unroll
        for (int j = 0; j < 4; j++) {
            __nv_bfloat16 h0 = __float2bfloat16_rn(f[2*j]);
            __nv_bfloat16 h1 = __float2bfloat16_rn(f[2*j+1]);
            float r0 = f[2*j]   - __bfloat162float(h0);
            float r1 = f[2*j+1] - __bfloat162float(h1);
            u1[j] = pack_bf(h0, h1);
            u2[j] = pack_bf(__float2bfloat16_rn(r0), __float2bfloat16_rn(r1));
        }
        uint32_t off = sw128(blk_off(row, c8 * 8));
        *(uint4*)(smem + OFF_X1 + off) = make_uint4(u1[0], u1[1], u1[2], u1[3]);
        *(uint4*)(smem + OFF_X2 + off) = make_uint4(u2[0], u2[1], u2[2], u2[3]);
    }

    /* prologue: async-load e tile 0 into buf0 */
    #pragma unroll
    for (int r = 0; r < 4; r++) {
        int i = tid + r * DTHREADS;
        int row = i >> 4, c8 = i & 15;
        uint32_t off = sw128(blk_off(row, c8 * 8));
        const char* s1 = (const char*)(g_eb1 + (size_t)row * DDIM + c8 * 8);
        const char* s2 = (const char*)(g_eb2 + (size_t)row * DDIM + c8 * 8);
        CP16(sb + OFF_E0 + off, s1);
        CP16(sb + OFF_E0 + 32768 + off, s2);
    }
    if (tid < BN) es2[tid] = g_e2[tid];
    CP_COMMIT();

    float m1[4], m2[4]; int i1[4];
    #pragma unroll
    for (int r = 0; r < 4; r++) { m1[r] = -FLT_MAX; m2[r] = -FLT_MAX; i1[r] = 0; }

    for (int b = 0; b < NBLK; b++) {
        __syncthreads();   /* prev-iter readers of next buffer done */
        if (b + 1 < NBLK) {
            uint32_t eb = sb + ((b + 1) & 1 ? OFF_E1 : OFF_E0);
            #pragma unroll
            for (int r = 0; r < 4; r++) {
                int i = tid + r * DTHREADS;
                int row = i >> 4, c8 = i & 15;
                uint32_t off = sw128(blk_off(row, c8 * 8));
                size_t g = (size_t)((b + 1) * BN + row) * DDIM + c8 * 8;
                CP16(eb + off, (const char*)(g_eb1 + g));
                CP16(eb + 32768 + off, (const char*)(g_eb2 + g));
            }
            if (tid < BN) es2[((b + 1) & 1) * BN + tid] = g_e2[(b + 1) * BN + tid];
            CP_COMMIT();
            CP_WAIT(1);
        } else {
            CP_WAIT(0);
        }
        __syncthreads();   /* buffer b + es2[b] visible */

        const uint32_t e1b = sb + (b & 1 ? OFF_E1 : OFF_E0);
        const uint32_t e2b = e1b + 32768;
        const float* es2c = es2 + (b & 1) * BN;

        float acc[2][4][4];
        #pragma unroll
        for (int m = 0; m < 2; m++)
            #pragma unroll
            for (int j = 0; j < 4; j++)
                #pragma unroll
                for (int c = 0; c < 4; c++) acc[m][j][c] = 0.f;

        #pragma unroll
        for (int s = 0; s < 8; s++) {
            int k0 = s * 16;
            uint32_t a1[2][4], a2[2][4], q1[2][4], q2[2][4];
            #pragma unroll
            for (int m = 0; m < 2; m++) {
                uint32_t off = sw128(blk_off(wr * 32 + m * 16 + lrow, k0 + lcol));
                ldsm4(a1[m], sb + OFF_X1 + off);
                ldsm4(a2[m], sb + OFF_X2 + off);
            }
            #pragma unroll
            for (int t = 0; t < 2; t++) {
                uint32_t off = sw128(blk_off(wc * 32 + t * 16 + lrow, k0 + lcol));
                ldsm4(q1[t], e1b + off);
                ldsm4(q2[t], e2b + off);
            }
            #pragma unroll
            for (int m = 0; m < 2; m++)
                #pragma unroll
                for (int j = 0; j < 4; j++) {
                    int t = j >> 1, h = j & 1;
                    mma16816(acc[m][j], a1[m], q1[t][h], q1[t][h + 2]);
                    mma16816(acc[m][j], a1[m], q2[t][h], q2[t][h + 2]);
                    mma16816(acc[m][j], a2[m], q1[t][h], q1[t][h + 2]);
                }
        }

        /* argmax epilogue: k ascending per (lane,row) => strict '>' = first max */
        #pragma unroll
        for (int m = 0; m < 2; m++)
            #pragma unroll
            for (int j = 0; j < 4; j++) {
                int col = wc * 32 + j * 8 + tig * 2;
                float2 ee = *(const float2*)(es2c + col);
                int k = b * BN + col;
                #pragma unroll
                for (int h = 0; h < 2; h++) {
                    int r4 = m * 2 + h;
                    float v0 = fmaf(2.f, acc[m][j][h * 2 + 0], -ee.x);
                    float v1 = fmaf(2.f, acc[m][j][h * 2 + 1], -ee.y);
                    if (v0 > m1[r4]) { m2[r4] = m1[r4]; m1[r4] = v0; i1[r4] = k; }
                    else if (v0 > m2[r4]) m2[r4] = v0;
                    if (v1 > m1[r4]) { m2[r4] = m1[r4]; m1[r4] = v1; i1[r4] = k + 1; }
                    else if (v1 > m2[r4]) m2[r4] = v1;
                }
            }
    }

    /* cross-lane / cross-warp reduction via smem (reuse e buffers) */
    __syncthreads();
    float* red_m1 = (float*)(smem + OFF_E0);            /* [128][16] */
    float* red_m2 = red_m1 + BM * 16;
    int*   red_i1 = (int*)(red_m2 + BM * 16);
    #pragma unroll
    for (int r4 = 0; r4 < 4; r4++) {
        int row = wr * 32 + (r4 >> 1) * 16 + (r4 & 1) * 8 + gid;
        int slot = wc * 4 + tig;
        red_m1[row * 16 + slot] = m1[r4];
        red_m2[row * 16 + slot] = m2[r4];
        red_i1[row * 16 + slot] = i1[r4];
    }
    __syncthreads();
    if (tid < BM) {
        float bm1 = -FLT_MAX, bm2 = -FLT_MAX; int bi = 0x7fffffff;
        #pragma unroll
        for (int s = 0; s < 16; s++) {
            float em1 = red_m1[tid * 16 + s];
            float em2 = red_m2[tid * 16 + s];
            int   ei  = red_i1[tid * 16 + s];
            if (em1 > bm1 || (em1 == bm1 && ei < bi)) {
                bm2 = fmaxf(bm1, em2); bm1 = em1; bi = ei;
            } else {
                bm2 = fmaxf(bm2, em1);
            }
        }
        int row = row0 + tid;
        g_idx[row]   = bi;
        out_ind[row] = (float)bi;
        g_flag[row]  = (bm1 - bm2 < MARGIN) ? 1 : 0;
    }
}

/* ------------------------------------------------------------------ */
/* exact fp32 rescue for flagged rows: one warp per row                */
/* ------------------------------------------------------------------ */
__global__ void fixer_kernel(const float* __restrict__ x,
                             const float* __restrict__ embed,
                             float* __restrict__ out_ind) {
    int w = (blockIdx.x * blockDim.x + threadIdx.x) >> 5;
    int lane = threadIdx.x & 31;
    if (w >= NROWS || !g_flag[w]) return;
    float4 xv = *((const float4*)(x + (size_t)w * DDIM) + lane);
    float best = -FLT_MAX; int bi = 0;
    for (int k = 0; k < KCODES; k++) {
        float4 ev = *((const float4*)(embed + (size_t)k * DDIM) + lane);
        float p = xv.x * ev.x + xv.y * ev.y + xv.z * ev.z + xv.w * ev.w;
        #pragma unroll
        for (int o = 16; o; o >>= 1) p += __shfl_xor_sync(0xffffffffu, p, o);
        float s = 2.f * p - g_e2[k];
        if (s > best) { best = s; bi = k; }   /* first max wins */
    }
    if (lane == 0) { g_idx[w] = bi; out_ind[w] = (float)bi; }
}

/* ------------------------------------------------------------------ */
/* epilogue kernels                                                    */
/* ------------------------------------------------------------------ */
__global__ void gather_kernel(const float* __restrict__ embed,
                              float* __restrict__ out_q) {
    int t = blockIdx.x * blockDim.x + threadIdx.x;
    int n = t >> 5, c = t & 31;
    int k = g_idx[n];
    float4 v = *((const float4*)(embed + (size_t)k * DDIM) + c);
    *((float4*)(out_q + (size_t)n * DDIM) + c) = v;
}

__global__ void init_kernel(const float* __restrict__ cluster_size,
                            const float* __restrict__ embed_avg,
                            float* __restrict__ out_cs,
                            float* __restrict__ out_avg) {
    int i = blockIdx.x * blockDim.x + threadIdx.x;
    float4 v = *((const float4*)embed_avg + i);
    v.x *= DECAY; v.y *= DECAY; v.z *= DECAY; v.w *= DECAY;
    *((float4*)out_avg + i) = v;
    if (i < KCODES) out_cs[i] = cluster_size[i] * DECAY;
}

__global__ void scatter_kernel(const float* __restrict__ x,
                               float* __restrict__ out_cs,
                               float* __restrict__ out_avg) {
    int t = blockIdx.x * blockDim.x + threadIdx.x;
    int n = t >> 5, lane = t & 31;
    int k = g_idx[n];
    float4 v = *((const float4*)(x + (size_t)n * DDIM) + lane);
    float* dst = out_avg + (size_t)k * DDIM + lane * 4;
    atomicAdd(dst + 0, OMD * v.x);
    atomicAdd(dst + 1, OMD * v.y);
    atomicAdd(dst + 2, OMD * v.z);
    atomicAdd(dst + 3, OMD * v.w);
    if (lane == 0) atomicAdd(out_cs + k, OMD);
}

__global__ void finalize1_kernel(const float* __restrict__ out_cs) {
    __shared__ float red[KCODES];
    int tid = threadIdx.x;
    float c = out_cs[tid];
    red[tid] = c;
    __syncthreads();
    for (int s = 512; s; s >>= 1) {
        if (tid < s) red[tid] += red[tid + s];
        __syncthreads();
    }
    float total = red[0];
    g_sm[tid] = (c + EPS) / (total + KCODES * EPS) * total;
}

__global__ void finalize2_kernel(const float* __restrict__ out_avg,
                                 float* __restrict__ out_ne) {
    int i = blockIdx.x * blockDim.x + threadIdx.x;
    float sm = g_sm[i >> 5];
    float4 v = *((const float4*)out_avg + i);
    v.x /= sm; v.y /= sm; v.z /= sm; v.w /= sm;
    *((float4*)out_ne + i) = v;
}

/* ------------------------------------------------------------------ */
extern "C" void kernel_launch(void* const* d_in, const int* in_sizes, int n_in,
                              void* d_out, int out_size) {
    const float* x            = (const float*)d_in[0];
    const float* embed        = (const float*)d_in[1];
    const float* cluster_size = (const float*)d_in[2];
    const float* embed_avg    = (const float*)d_in[3];

    float* out      = (float*)d_out;
    float* out_q    = out;                               /* 32768*128 */
    float* out_ind  = out_q  + (size_t)NROWS * DDIM;     /* 32768     */
    float* out_cs   = out_ind + NROWS;                   /* 1024      */
    float* out_avg  = out_cs + KCODES;                   /* 1024*128  */
    float* out_ne   = out_avg + (size_t)KCODES * DDIM;   /* 1024*128  */

    cudaFuncSetAttribute(dist_mma_kernel,
                         cudaFuncAttributeMaxDynamicSharedMemorySize, SMEM_TOTAL);

    e_split_kernel<<<KCODES * 32 / THREADS, THREADS>>>(embed);
    dist_mma_kernel<<<NROWS / BM, DTHREADS, SMEM_TOTAL>>>(x, out_ind);
    fixer_kernel<<<NROWS * 32 / THREADS, THREADS>>>(x, embed, out_ind);
    gather_kernel<<<NROWS * 32 / THREADS, THREADS>>>(embed, out_q);
    init_kernel<<<KCODES * DDIM / 4 / THREADS, THREADS>>>(cluster_size, embed_avg,
                                                          out_cs, out_avg);
    scatter_kernel<<<NROWS * 32 / THREADS, THREADS>>>(x, out_cs, out_avg);
    finalize1_kernel<<<1, KCODES>>>(out_cs);
    finalize2_kernel<<<KCODES * DDIM / 4 / THREADS, THREADS>>>(out_avg, out_ne);
}

// round 9
// speedup vs baseline: 1.6784x; 1.6784x over previous
#include <cuda_runtime.h>
#include <cuda_fp16.h>
#include <stdint.h>
#include <float.h>

#define DECAY 0.99f
#define OMD   0.01f
#define EPS   1e-5f
#define NROWS 32768
#define DDIM  128
#define KCODES 1024
#define BM 128                   /* rows per CTA  */
#define BN 128                   /* codes per tile */
#define NBLK (KCODES / BN)       /* 8 */
#define THREADS 256
#define MARGIN 0.05f

/* smem byte offsets */
#define OFF_X1   0               /* 128x128 fp16 swizzled, 32KB */
#define OFF_E1   32768           /* 32KB */
#define OFF_E2   65536           /* 32KB */
#define OFF_ES2  98304           /* 128 floats */
#define SMEM_TOTAL (98304 + 512)

typedef unsigned long long ull;

/* scratch (no device mallocs allowed) */
__device__ float         g_e2[KCODES];
__device__ int           g_idx[NROWS];
__device__ float         g_sm[KCODES];
__device__ __half        g_eh1[KCODES * DDIM];
__device__ __half        g_eh2[KCODES * DDIM];
__device__ unsigned char g_flag[NROWS];

/* ------------------------------------------------------------------ */
__device__ __forceinline__ uint32_t smem_u32(const void* p) {
    uint32_t a;
    asm("{ .reg .u64 t; cvta.to.shared.u64 t, %1; cvt.u32.u64 %0, t; }"
        : "=r"(a) : "l"(p));
    return a;
}
__device__ __forceinline__ uint32_t sw128(uint32_t off) {
    return off ^ ((off >> 3) & 0x70);
}
/* blocked SW128 atom layout for [128 rows x 128 fp16] K-major tile */
__device__ __forceinline__ uint32_t blk_off(int r, int c) {
    return ((uint32_t)((c >> 6) * 16 + (r >> 3)) << 10)
         + ((uint32_t)(r & 7) << 7) + ((uint32_t)(c & 63) << 1);
}
__device__ __forceinline__ uint32_t pack_h(__half lo, __half hi) {
    uint16_t l = *reinterpret_cast<uint16_t*>(&lo);
    uint16_t h = *reinterpret_cast<uint16_t*>(&hi);
    return ((uint32_t)h << 16) | l;
}
__device__ __forceinline__ void ldsm4(uint32_t* r, uint32_t addr) {
    asm volatile("ldmatrix.sync.aligned.m8n8.x4.shared.b16 {%0,%1,%2,%3}, [%4];"
                 : "=r"(r[0]), "=r"(r[1]), "=r"(r[2]), "=r"(r[3]) : "r"(addr));
}
__device__ __forceinline__ void mma16816(float* d, const uint32_t* a,
                                         uint32_t b0, uint32_t b1) {
    asm volatile(
        "mma.sync.aligned.m16n8k16.row.col.f32.f16.f16.f32 "
        "{%0,%1,%2,%3}, {%4,%5,%6,%7}, {%8,%9}, {%0,%1,%2,%3};"
        : "+f"(d[0]), "+f"(d[1]), "+f"(d[2]), "+f"(d[3])
        : "r"(a[0]), "r"(a[1]), "r"(a[2]), "r"(a[3]), "r"(b0), "r"(b1));
}
#define CP16(dst, src) \
    asm volatile("cp.async.cg.shared.global [%0], [%1], 16;" \
                 :: "r"(dst), "l"(src) : "memory")
#define CP_COMMIT() asm volatile("cp.async.commit_group;" ::: "memory")
#define CP_WAIT(n)  asm volatile("cp.async.wait_group %0;" :: "n"(n) : "memory")

/* ------------------------------------------------------------------ */
/* embed prep: fp16 split + ||e||^2. one warp per code.                */
/* ------------------------------------------------------------------ */
__global__ void e_split_kernel(const float* __restrict__ embed) {
    int code = (blockIdx.x * blockDim.x + threadIdx.x) >> 5;
    int lane = threadIdx.x & 31;
    if (code >= KCODES) return;
    float4 a = *((const float4*)(embed + (size_t)code * DDIM) + lane);
    float f[4] = {a.x, a.y, a.z, a.w};
    __half h1[4], h2[4];
    float s = 0.f;
    #pragma unroll
    for (int j = 0; j < 4; j++) {
        s += f[j] * f[j];
        h1[j] = __float2half_rn(f[j]);
        float r = f[j] - __half2float(h1[j]);
        h2[j] = __float2half_rn(r);
    }
    uint32_t* d1 = (uint32_t*)(g_eh1 + (size_t)code * DDIM + lane * 4);
    uint32_t* d2 = (uint32_t*)(g_eh2 + (size_t)code * DDIM + lane * 4);
    d1[0] = pack_h(h1[0], h1[1]); d1[1] = pack_h(h1[2], h1[3]);
    d2[0] = pack_h(h2[0], h2[1]); d2[1] = pack_h(h2[2], h2[3]);
    #pragma unroll
    for (int o = 16; o; o >>= 1) s += __shfl_xor_sync(0xffffffffu, s, o);
    if (lane == 0) g_e2[code] = s;
}

/* ------------------------------------------------------------------ */
/* fp16 2-pass mma.sync distance + approx argmax with margin flag      */
/* 256 threads, 8 warps, warp grid 4x2, warp tile 32x64                */
/* ------------------------------------------------------------------ */
__global__ void __launch_bounds__(THREADS, 2)
dist_mma_kernel(const float* __restrict__ x, float* __restrict__ out_ind) {
    extern __shared__ char smem[];
    const uint32_t sb = smem_u32(smem);
    const int tid  = threadIdx.x;
    const int wid  = tid >> 5, lane = tid & 31;
    const int wr   = wid & 3, wc = wid >> 2;      /* warp grid 4x2 */
    const int gid  = lane >> 2, tig = lane & 3;
    const int lrow = lane & 15, lcol = (lane >> 4) << 3;
    const int row0 = blockIdx.x * BM;
    float* es2 = (float*)(smem + OFF_ES2);        /* [128] */

    /* x tile: convert to fp16 (hi only), store swizzled */
    #pragma unroll
    for (int it = 0; it < 8; it++) {
        int i = tid + it * THREADS;
        int row = i >> 4, c8 = i & 15;
        const float* xp = x + (size_t)(row0 + row) * DDIM + c8 * 8;
        float4 fa = *(const float4*)xp;
        float4 fb = *(const float4*)(xp + 4);
        float f[8] = {fa.x, fa.y, fa.z, fa.w, fb.x, fb.y, fb.z, fb.w};
        uint32_t u1[4];
        #pragma unroll
        for (int j = 0; j < 4; j++)
            u1[j] = pack_h(__float2half_rn(f[2*j]), __float2half_rn(f[2*j+1]));
        uint32_t off = sw128(blk_off(row, c8 * 8));
        *(uint4*)(smem + OFF_X1 + off) = make_uint4(u1[0], u1[1], u1[2], u1[3]);
    }

    float m1[4], m2[4]; int i1[4];
    #pragma unroll
    for (int r = 0; r < 4; r++) { m1[r] = -FLT_MAX; m2[r] = -FLT_MAX; i1[r] = 0; }

    for (int b = 0; b < NBLK; b++) {
        __syncthreads();   /* previous iteration's compute done: E free */
        /* load e tiles (fp16 hi + residual), swizzled: 16 CP16/thread */
        #pragma unroll
        for (int r = 0; r < 8; r++) {
            int i = tid + r * THREADS;
            int row = i >> 4, c8 = i & 15;
            uint32_t off = sw128(blk_off(row, c8 * 8));
            size_t g = (size_t)(b * BN + row) * DDIM + c8 * 8;
            CP16(sb + OFF_E1 + off, (const char*)(g_eh1 + g));
            CP16(sb + OFF_E2 + off, (const char*)(g_eh2 + g));
        }
        if (tid < BN) es2[tid] = g_e2[b * BN + tid];
        CP_COMMIT();
        CP_WAIT(0);
        __syncthreads();

        float acc[2][8][4];
        #pragma unroll
        for (int m = 0; m < 2; m++)
            #pragma unroll
            for (int j = 0; j < 8; j++)
                #pragma unroll
                for (int c = 0; c < 4; c++) acc[m][j][c] = 0.f;

        #pragma unroll
        for (int s = 0; s < 8; s++) {
            int k0 = s * 16;
            uint32_t a1[2][4];
            #pragma unroll
            for (int m = 0; m < 2; m++) {
                uint32_t off = sw128(blk_off(wr * 32 + m * 16 + lrow, k0 + lcol));
                ldsm4(a1[m], sb + OFF_X1 + off);
            }
            #pragma unroll
            for (int t = 0; t < 4; t++) {
                uint32_t q1[4], q2[4];
                uint32_t off = sw128(blk_off(wc * 64 + t * 16 + lrow, k0 + lcol));
                ldsm4(q1, sb + OFF_E1 + off);
                ldsm4(q2, sb + OFF_E2 + off);
                #pragma unroll
                for (int m = 0; m < 2; m++)
                    #pragma unroll
                    for (int h = 0; h < 2; h++) {
                        mma16816(acc[m][t * 2 + h], a1[m], q1[h], q1[h + 2]);
                        mma16816(acc[m][t * 2 + h], a1[m], q2[h], q2[h + 2]);
                    }
            }
        }

        /* argmax epilogue: k ascending per (lane,row) => strict '>' = first max */
        #pragma unroll
        for (int m = 0; m < 2; m++)
            #pragma unroll
            for (int j = 0; j < 8; j++) {
                int col = wc * 64 + j * 8 + tig * 2;
                float2 ee = *(const float2*)(es2 + col);
                int k = b * BN + col;
                #pragma unroll
                for (int h = 0; h < 2; h++) {
                    int r4 = m * 2 + h;
                    float v0 = fmaf(2.f, acc[m][j][h * 2 + 0], -ee.x);
                    float v1 = fmaf(2.f, acc[m][j][h * 2 + 1], -ee.y);
                    if (v0 > m1[r4]) { m2[r4] = m1[r4]; m1[r4] = v0; i1[r4] = k; }
                    else if (v0 > m2[r4]) m2[r4] = v0;
                    if (v1 > m1[r4]) { m2[r4] = m1[r4]; m1[r4] = v1; i1[r4] = k + 1; }
                    else if (v1 > m2[r4]) m2[r4] = v1;
                }
            }
    }

    /* cross-warp reduction: 8 candidates per row (reuse E region) */
    __syncthreads();
    float* red_m1 = (float*)(smem + OFF_E1);            /* [128][8] */
    float* red_m2 = red_m1 + BM * 8;
    int*   red_i1 = (int*)(red_m2 + BM * 8);
    #pragma unroll
    for (int r4 = 0; r4 < 4; r4++) {
        int row = wr * 32 + (r4 >> 1) * 16 + (r4 & 1) * 8 + gid;
        int slot = wc * 4 + tig;
        red_m1[row * 8 + slot] = m1[r4];
        red_m2[row * 8 + slot] = m2[r4];
        red_i1[row * 8 + slot] = i1[r4];
    }
    __syncthreads();
    if (tid < BM) {
        float bm1 = -FLT_MAX, bm2 = -FLT_MAX; int bi = 0x7fffffff;
        #pragma unroll
        for (int s = 0; s < 8; s++) {
            float em1 = red_m1[tid * 8 + s];
            float em2 = red_m2[tid * 8 + s];
            int   ei  = red_i1[tid * 8 + s];
            if (em1 > bm1 || (em1 == bm1 && ei < bi)) {
                bm2 = fmaxf(bm1, em2); bm1 = em1; bi = ei;
            } else {
                bm2 = fmaxf(bm2, em1);
            }
        }
        int row = row0 + tid;
        g_idx[row]   = bi;
        out_ind[row] = (float)bi;
        g_flag[row]  = (bm1 - bm2 < MARGIN) ? 1 : 0;
    }
}

/* ------------------------------------------------------------------ */
/* exact fp32 rescue for flagged rows: one warp per row                */
/* ------------------------------------------------------------------ */
__global__ void fixer_kernel(const float* __restrict__ x,
                             const float* __restrict__ embed,
                             float* __restrict__ out_ind) {
    int w = (blockIdx.x * blockDim.x + threadIdx.x) >> 5;
    int lane = threadIdx.x & 31;
    if (w >= NROWS || !g_flag[w]) return;
    float4 xv = *((const float4*)(x + (size_t)w * DDIM) + lane);
    float best = -FLT_MAX; int bi = 0;
    for (int k = 0; k < KCODES; k++) {
        float4 ev = *((const float4*)(embed + (size_t)k * DDIM) + lane);
        float p = xv.x * ev.x + xv.y * ev.y + xv.z * ev.z + xv.w * ev.w;
        #pragma unroll
        for (int o = 16; o; o >>= 1) p += __shfl_xor_sync(0xffffffffu, p, o);
        float s = 2.f * p - g_e2[k];
        if (s > best) { best = s; bi = k; }   /* first max wins */
    }
    if (lane == 0) { g_idx[w] = bi; out_ind[w] = (float)bi; }
}

/* ------------------------------------------------------------------ */
/* epilogue kernels                                                    */
/* ------------------------------------------------------------------ */
__global__ void gather_kernel(const float* __restrict__ embed,
                              float* __restrict__ out_q) {
    int t = blockIdx.x * blockDim.x + threadIdx.x;
    int n = t >> 5, c = t & 31;
    int k = g_idx[n];
    float4 v = *((const float4*)(embed + (size_t)k * DDIM) + c);
    *((float4*)(out_q + (size_t)n * DDIM) + c) = v;
}

__global__ void init_kernel(const float* __restrict__ cluster_size,
                            const float* __restrict__ embed_avg,
                            float* __restrict__ out_cs,
                            float* __restrict__ out_avg) {
    int i = blockIdx.x * blockDim.x + threadIdx.x;
    float4 v = *((const float4*)embed_avg + i);
    v.x *= DECAY; v.y *= DECAY; v.z *= DECAY; v.w *= DECAY;
    *((float4*)out_avg + i) = v;
    if (i < KCODES) out_cs[i] = cluster_size[i] * DECAY;
}

__global__ void scatter_kernel(const float* __restrict__ x,
                               float* __restrict__ out_cs,
                               float* __restrict__ out_avg) {
    int t = blockIdx.x * blockDim.x + threadIdx.x;
    int n = t >> 5, lane = t & 31;
    int k = g_idx[n];
    float4 v = *((const float4*)(x + (size_t)n * DDIM) + lane);
    float* dst = out_avg + (size_t)k * DDIM + lane * 4;
    atomicAdd(dst + 0, OMD * v.x);
    atomicAdd(dst + 1, OMD * v.y);
    atomicAdd(dst + 2, OMD * v.z);
    atomicAdd(dst + 3, OMD * v.w);
    if (lane == 0) atomicAdd(out_cs + k, OMD);
}

__global__ void finalize1_kernel(const float* __restrict__ out_cs) {
    __shared__ float red[KCODES];
    int tid = threadIdx.x;
    float c = out_cs[tid];
    red[tid] = c;
    __syncthreads();
    for (int s = 512; s; s >>= 1) {
        if (tid < s) red[tid] += red[tid + s];
        __syncthreads();
    }
    float total = red[0];
    g_sm[tid] = (c + EPS) / (total + KCODES * EPS) * total;
}

__global__ void finalize2_kernel(const float* __restrict__ out_avg,
                                 float* __restrict__ out_ne) {
    int i = blockIdx.x * blockDim.x + threadIdx.x;
    float sm = g_sm[i >> 5];
    float4 v = *((const float4*)out_avg + i);
    v.x /= sm; v.y /= sm; v.z /= sm; v.w /= sm;
    *((float4*)out_ne + i) = v;
}

/* ------------------------------------------------------------------ */
extern "C" void kernel_launch(void* const* d_in, const int* in_sizes, int n_in,
                              void* d_out, int out_size) {
    const float* x            = (const float*)d_in[0];
    const float* embed        = (const float*)d_in[1];
    const float* cluster_size = (const float*)d_in[2];
    const float* embed_avg    = (const float*)d_in[3];

    float* out      = (float*)d_out;
    float* out_q    = out;                               /* 32768*128 */
    float* out_ind  = out_q  + (size_t)NROWS * DDIM;     /* 32768     */
    float* out_cs   = out_ind + NROWS;                   /* 1024      */
    float* out_avg  = out_cs + KCODES;                   /* 1024*128  */
    float* out_ne   = out_avg + (size_t)KCODES * DDIM;   /* 1024*128  */

    cudaFuncSetAttribute(dist_mma_kernel,
                         cudaFuncAttributeMaxDynamicSharedMemorySize, SMEM_TOTAL);

    e_split_kernel<<<KCODES * 32 / THREADS, THREADS>>>(embed);
    dist_mma_kernel<<<NROWS / BM, THREADS, SMEM_TOTAL>>>(x, out_ind);
    fixer_kernel<<<NROWS * 32 / THREADS, THREADS>>>(x, embed, out_ind);
    gather_kernel<<<NROWS * 32 / THREADS, THREADS>>>(embed, out_q);
    init_kernel<<<KCODES * DDIM / 4 / THREADS, THREADS>>>(cluster_size, embed_avg,
                                                          out_cs, out_avg);
    scatter_kernel<<<NROWS * 32 / THREADS, THREADS>>>(x, out_cs, out_avg);
    finalize1_kernel<<<1, KCODES>>>(out_cs);
    finalize2_kernel<<<KCODES * DDIM / 4 / THREADS, THREADS>>>(out_avg, out_ne);
}